// round 15
// baseline (speedup 1.0000x reference)
#include <cuda_runtime.h>
#include <cstdint>

#define SEQ 2048
#define HD 64
#define NBH 32
#define TOPK 32
#define WPB 4
#define LCAP 128
#define CCAP 128
#define NROWS (NBH * SEQ)

typedef unsigned long long u64;

__device__ __forceinline__ u64 dup2(float x) {
    u64 r; asm("mov.b64 %0, {%1, %1};" : "=l"(r) : "f"(x)); return r;
}
__device__ __forceinline__ void fma2(u64& c, u64 a, u64 b) {
    asm("fma.rn.f32x2 %0, %1, %2, %0;" : "+l"(c) : "l"(a), "l"(b));
}
__device__ __forceinline__ unsigned fkey(float f) {
    unsigned u = __float_as_uint(f);
    return (u & 0x80000000u) ? ~u : (u | 0x80000000u);
}

// ---------------------------------------------------------------------------
// Kernel 1 (R10, measured ~571us): scores = (q/8).k via packed f32x2 FMA.
// 128(i) x 64(j) tile, 128 threads, 8x8 microtile. Prefills mask=1 (streaming).
// ---------------------------------------------------------------------------
__global__ __launch_bounds__(128) void score_kernel(
    const float* __restrict__ q, const float* __restrict__ k,
    float* __restrict__ scores, float* __restrict__ maskp)
{
    __shared__ float QsT[HD * 128];
    __shared__ float KsT[HD * 64];

    const int t = threadIdx.x;
    const int bh = blockIdx.z;
    const float* qb = q + ((size_t)bh * SEQ + blockIdx.y * 128) * HD;
    const float* kb = k + ((size_t)bh * SEQ + blockIdx.x * 64) * HD;

#pragma unroll
    for (int it = 0; it < 16; it++) {
        int idx = t + 128 * it;
        int d4 = idx >> 7, row = idx & 127;
        float4 val = *(const float4*)(qb + row * HD + d4 * 4);
        QsT[(d4 * 4 + 0) * 128 + row] = val.x * 0.125f;
        QsT[(d4 * 4 + 1) * 128 + row] = val.y * 0.125f;
        QsT[(d4 * 4 + 2) * 128 + row] = val.z * 0.125f;
        QsT[(d4 * 4 + 3) * 128 + row] = val.w * 0.125f;
    }
#pragma unroll
    for (int it = 0; it < 8; it++) {
        int idx = t + 128 * it;
        int d4 = idx >> 6, row = idx & 63;
        float4 val = *(const float4*)(kb + row * HD + d4 * 4);
        KsT[(d4 * 4 + 0) * 64 + row] = val.x;
        KsT[(d4 * 4 + 1) * 64 + row] = val.y;
        KsT[(d4 * 4 + 2) * 64 + row] = val.z;
        KsT[(d4 * 4 + 3) * 64 + row] = val.w;
    }
    __syncthreads();

    const int ti = t >> 3, tj = t & 7;
    u64 acc[8][4];
#pragma unroll
    for (int i = 0; i < 8; i++)
#pragma unroll
        for (int p = 0; p < 4; p++) acc[i][p] = 0ull;

    const float4* Q4 = (const float4*)QsT;
    const u64* K2 = (const u64*)KsT;

#pragma unroll 8
    for (int d = 0; d < HD; d++) {
        float4 a0 = Q4[d * 32 + ti * 2];
        float4 a1 = Q4[d * 32 + ti * 2 + 1];
        u64 b0 = K2[d * 32 + tj * 4 + 0];
        u64 b1 = K2[d * 32 + tj * 4 + 1];
        u64 b2 = K2[d * 32 + tj * 4 + 2];
        u64 b3 = K2[d * 32 + tj * 4 + 3];
        float av[8] = {a0.x, a0.y, a0.z, a0.w, a1.x, a1.y, a1.z, a1.w};
#pragma unroll
        for (int i = 0; i < 8; i++) {
            u64 ai = dup2(av[i]);
            fma2(acc[i][0], ai, b0);
            fma2(acc[i][1], ai, b1);
            fma2(acc[i][2], ai, b2);
            fma2(acc[i][3], ai, b3);
        }
    }

    const size_t obase = ((size_t)bh * SEQ + blockIdx.y * 128 + ti * 8) * SEQ
                       + blockIdx.x * 64 + tj * 8;
#pragma unroll
    for (int i = 0; i < 8; i++) {
        u64* o = (u64*)(scores + obase + (size_t)i * SEQ);
        o[0] = acc[i][0]; o[1] = acc[i][1]; o[2] = acc[i][2]; o[3] = acc[i][3];
    }
    if (maskp) {
        const float4 one4 = make_float4(1.f, 1.f, 1.f, 1.f);
#pragma unroll
        for (int i = 0; i < 8; i++) {
            float4* mo = (float4*)(maskp + obase + (size_t)i * SEQ);
            __stcs(mo, one4); __stcs(mo + 1, one4);
        }
    }
}

// Pick the bin (0..255) holding the kk-th largest, given a 256-bin histogram.
__device__ __forceinline__ void pick_bin(unsigned* H, int lane, unsigned kkin,
                                         unsigned& bin, unsigned& kkout)
{
    unsigned p = 0;
#pragma unroll
    for (int b = 0; b < 8; b++) p += H[lane * 8 + b];
    unsigned S = p;
#pragma unroll
    for (int off = 1; off < 32; off <<= 1) {
        unsigned tv = __shfl_down_sync(0xffffffffu, S, off);
        if (lane + off < 32) S += tv;
    }
    unsigned sufExcl = S - p;
    bool mine = (S >= kkin) && (sufExcl < kkin);
    unsigned bal = __ballot_sync(0xffffffffu, mine);
    int src = __ffs(bal) - 1;
    unsigned chosen = 0, newk = 0;
    if (mine) {
        unsigned cum = sufExcl;
#pragma unroll
        for (int b = 7; b >= 0; b--) {
            unsigned h = H[lane * 8 + b];
            if (cum + h >= kkin) { chosen = lane * 8 + b; newk = kkin - cum; break; }
            cum += h;
        }
    }
    bin = __shfl_sync(0xffffffffu, chosen, src);
    kkout = __shfl_sync(0xffffffffu, newk, src);
}

// ---------------------------------------------------------------------------
// Kernel 2: warp-per-row with a u16 key digest (top 16 bits) in smem.
// Rounds 1-2 exact on the digest; candidates (top16 == prefix16) refetched
// from the L2-hot gmem row for exact rounds 3-4 (UNIFORM-trip loops: all
// lanes execute match_any; inactive lanes use a unique sentinel bin).
// Ties in the keep-scan resolved by exact refetch. ALL gmem refetches precede
// the in-place attn=0 fill (attn aliases scores). 26KB smem -> ~8 blocks/SM.
// ---------------------------------------------------------------------------
__global__ __launch_bounds__(WPB * 32) void finalize_kernel(
    const float* __restrict__ v, const float* __restrict__ scores,
    float* __restrict__ ctx, float* __restrict__ attn, float* __restrict__ maskp)
{
    __shared__ unsigned short srow16[WPB][SEQ];   // 16 KB
    __shared__ unsigned hist[WPB][256];           // 4 KB
    __shared__ unsigned candk[WPB][CCAP];         // 2 KB
    __shared__ int list[WPB][LCAP];               // 2 KB
    __shared__ float plist[WPB][LCAP];            // 2 KB

    const int w = threadIdx.x >> 5;
    const int lane = threadIdx.x & 31;
    const size_t R = (size_t)(NROWS - 1) - ((size_t)blockIdx.x * WPB + w);
    const int bh = (int)(R >> 11);
    const float* grow = scores + R * SEQ;
    unsigned* H = hist[w];

    // All call sites are in warp-uniform-trip loops; inactive lanes feed a
    // unique sentinel (0x100+lane) so match_any is always fully converged.
#define HAGG(binv, active) { unsigned _b = (binv); bool _a = (active);           \
        unsigned _key = _a ? _b : (0x100u + lane);                               \
        unsigned _mm = __match_any_sync(0xffffffffu, _key);                      \
        if (_a && (unsigned)(__ffs(_mm) - 1) == (unsigned)lane)                  \
            atomicAdd(&H[_b], __popc(_mm)); }

    // ---- Pass 1: digest + exact max + top-byte histogram ----
#pragma unroll
    for (int e = 0; e < 8; e++) H[lane + 32 * e] = 0;
    __syncwarp();
    const float4* g4 = (const float4*)grow;
    float m = __int_as_float(0xff800000);
#pragma unroll 4
    for (int it = 0; it < 16; it++) {
        float4 val = g4[lane + 32 * it];
        m = fmaxf(m, fmaxf(fmaxf(val.x, val.y), fmaxf(val.z, val.w)));
        unsigned k0 = fkey(val.x), k1 = fkey(val.y), k2 = fkey(val.z), k3 = fkey(val.w);
        ushort4 h4;
        h4.x = (unsigned short)(k0 >> 16); h4.y = (unsigned short)(k1 >> 16);
        h4.z = (unsigned short)(k2 >> 16); h4.w = (unsigned short)(k3 >> 16);
        ((ushort4*)srow16[w])[lane + 32 * it] = h4;
        HAGG(k0 >> 24, true); HAGG(k1 >> 24, true);
        HAGG(k2 >> 24, true); HAGG(k3 >> 24, true);
    }
#pragma unroll
    for (int off = 16; off >= 1; off >>= 1)
        m = fmaxf(m, __shfl_xor_sync(0xffffffffu, m, off));
    __syncwarp();

    // ---- Round 1 ----
    unsigned kk = TOPK, b1, b2;
    pick_bin(H, lane, kk, b1, kk);
    __syncwarp();

    // ---- Round 2: byte2 histogram over digest where top byte == b1 ----
#pragma unroll
    for (int e = 0; e < 8; e++) H[lane + 32 * e] = 0;
    __syncwarp();
    const unsigned* s32 = (const unsigned*)srow16[w];   // 1024 packed pairs
#pragma unroll 4
    for (int it = 0; it < 32; it++) {
        unsigned u = s32[lane + 32 * it];
        unsigned lo = u & 0xFFFFu, hi = u >> 16;
        HAGG(lo & 255u, (lo >> 8) == b1);
        HAGG(hi & 255u, (hi >> 8) == b1);
    }
    __syncwarp();
    pick_bin(H, lane, kk, b2, kk);
    const unsigned prefix16 = (b1 << 8) | b2;
    __syncwarp();

    // ---- Collect candidates (digest == prefix16): exact keys via refetch ----
    int cbase = 0;
    for (int it = 0; it < 32; it++) {
        unsigned u = s32[lane + 32 * it];
#pragma unroll
        for (int h = 0; h < 2; h++) {
            unsigned hv = h ? (u >> 16) : (u & 0xFFFFu);
            int j = (lane + 32 * it) * 2 + h;
            bool isc = (hv == prefix16);
            unsigned bal = __ballot_sync(0xffffffffu, isc);
            if (isc) {
                int pos = cbase + __popc(bal & ((1u << lane) - 1u));
                if (pos < CCAP) candk[w][pos] = fkey(__ldg(&grow[j]));
            }
            cbase += __popc(bal);
        }
    }
    __syncwarp();

    unsigned tkey;
    if (cbase <= CCAP) {
        const int c = cbase;
        // ---- Round 3 over candidates (byte1 of exact key); uniform trips ----
#pragma unroll
        for (int e = 0; e < 8; e++) H[lane + 32 * e] = 0;
        __syncwarp();
        for (int e0 = 0; e0 < c; e0 += 32) {
            int e = e0 + lane;
            bool valid = e < c;
            unsigned u = valid ? candk[w][e] : 0u;
            HAGG((u >> 8) & 255u, valid);
        }
        __syncwarp();
        unsigned b3;
        pick_bin(H, lane, kk, b3, kk);
        __syncwarp();
        // ---- Round 4 (byte0 where byte1 == b3); uniform trips ----
#pragma unroll
        for (int e = 0; e < 8; e++) H[lane + 32 * e] = 0;
        __syncwarp();
        for (int e0 = 0; e0 < c; e0 += 32) {
            int e = e0 + lane;
            bool valid = e < c;
            unsigned u = valid ? candk[w][e] : 0u;
            HAGG(u & 255u, valid && (((u >> 8) & 255u) == b3));
        }
        __syncwarp();
        unsigned b4, kkd;
        pick_bin(H, lane, kk, b4, kkd);
        tkey = (prefix16 << 16) | (b3 << 8) | b4;
    } else {
        // Exact fallback (pathological tie storm): full-row rounds 3-4 from gmem.
        unsigned prefix = prefix16 << 16, prefmask = 0xFFFF0000u;
#pragma unroll
        for (int shift = 8; shift >= 0; shift -= 8) {
#pragma unroll
            for (int e = 0; e < 8; e++) H[lane + 32 * e] = 0;
            __syncwarp();
            for (int it = 0; it < 16; it++) {
                float4 val = g4[lane + 32 * it];
                unsigned ks[4] = {fkey(val.x), fkey(val.y), fkey(val.z), fkey(val.w)};
#pragma unroll
                for (int cc = 0; cc < 4; cc++)
                    HAGG((ks[cc] >> shift) & 255u, (ks[cc] & prefmask) == prefix);
            }
            __syncwarp();
            unsigned bsel;
            pick_bin(H, lane, kk, bsel, kk);
            prefix |= bsel << shift;
            prefmask |= 0xFFu << shift;
            __syncwarp();
        }
        tkey = prefix;
    }
    const unsigned thr16 = tkey >> 16;   // == prefix16
    __syncwarp();

    // ---- Keep-scan (digest; ties resolved by exact refetch) ----
    int base = 0;
    for (int it = 0; it < 32; it++) {
        unsigned u = s32[lane + 32 * it];
#pragma unroll
        for (int h = 0; h < 2; h++) {
            unsigned hv = h ? (u >> 16) : (u & 0xFFFFu);
            int j = (lane + 32 * it) * 2 + h;
            bool keep = (hv > thr16);
            if (hv == thr16) keep = fkey(__ldg(&grow[j])) >= tkey;
            unsigned bal = __ballot_sync(0xffffffffu, keep);
            if (keep) {
                int pos = base + __popc(bal & ((1u << lane) - 1u));
                if (pos < LCAP) list[w][pos] = j;
            }
            base += __popc(bal);
        }
    }
    __syncwarp();
    const int n = base < LCAP ? base : LCAP;

    // ---- exp on kept (raw scores from L1/L2-hot gmem, BEFORE the fill) ----
    float lsum = 0.f;
    for (int e = lane; e < n; e += 32) {
        float s = __ldg(&grow[list[w][e]]);
        float p = __expf(s - m);
        plist[w][e] = p;
        lsum += p;
    }
#pragma unroll
    for (int off = 16; off >= 1; off >>= 1)
        lsum += __shfl_xor_sync(0xffffffffu, lsum, off);
    const float inv = 1.0f / lsum;
    __syncwarp();

    // ---- attn = 0 fill (in-place overwrite of the score row) ----
    float4* a4 = (float4*)(attn + R * SEQ);
    const float4 zero4 = make_float4(0.f, 0.f, 0.f, 0.f);
#pragma unroll
    for (int it = 0; it < 16; it++) __stcs(&a4[lane + 32 * it], zero4);

    // ---- Scatter kept attn / mask=0; dual-accumulator V gather ----
    const float* vb = v + (size_t)bh * SEQ * HD;
    float acc0a = 0.f, acc1a = 0.f, acc0b = 0.f, acc1b = 0.f;
    float* arow = attn + R * SEQ;
    float* mrow = maskp ? maskp + R * SEQ : (float*)0;
    int e = 0;
    for (; e + 1 < n; e += 2) {
        int j0 = list[w][e], j1 = list[w][e + 1];
        float w0 = plist[w][e] * inv, w1 = plist[w][e + 1] * inv;
        float v00 = __ldg(vb + j0 * HD + lane);
        float v01 = __ldg(vb + j0 * HD + lane + 32);
        float v10 = __ldg(vb + j1 * HD + lane);
        float v11 = __ldg(vb + j1 * HD + lane + 32);
        if (lane == 0) {
            arow[j0] = w0; arow[j1] = w1;
            if (mrow) { mrow[j0] = 0.f; mrow[j1] = 0.f; }
        }
        acc0a += w0 * v00; acc1a += w0 * v01;
        acc0b += w1 * v10; acc1b += w1 * v11;
    }
    if (e < n) {
        int j0 = list[w][e];
        float w0 = plist[w][e] * inv;
        if (lane == 0) {
            arow[j0] = w0;
            if (mrow) mrow[j0] = 0.f;
        }
        acc0a += w0 * __ldg(vb + j0 * HD + lane);
        acc1a += w0 * __ldg(vb + j0 * HD + lane + 32);
    }
    if (ctx) {
        ctx[R * HD + lane] = acc0a + acc0b;
        ctx[R * HD + lane + 32] = acc1a + acc1b;
    }
#undef HAGG
}

// ---------------------------------------------------------------------------
extern "C" void kernel_launch(void* const* d_in, const int* in_sizes, int n_in,
                              void* d_out, int out_size)
{
    if (n_in < 3 || !d_out) return;
    const float* q = (const float*)d_in[0];
    const float* k = (const float*)d_in[1];
    const float* v = (const float*)d_in[2];
    float* out = (float*)d_out;

    const size_t nctx = (size_t)NBH * SEQ * HD;        //   4,194,304
    const size_t nattn = (size_t)NBH * SEQ * SEQ;      // 134,217,728
    float* ctx = 0; float* attn = 0; float* maskp = 0;
    const size_t osz = (size_t)out_size;
    if (osz >= nctx + 2 * nattn) {
        ctx = out; attn = out + nctx; maskp = out + nctx + nattn;
    } else if (osz >= nctx + nattn) {
        ctx = out; attn = out + nctx;
    } else {
        attn = out;
    }

    // Kernel 1 stages raw scores in the attn segment and prefills mask = 1.
    score_kernel<<<dim3(SEQ / 64, SEQ / 128, NBH), 128>>>(q, k, attn, maskp);
    finalize_kernel<<<NROWS / WPB, WPB * 32>>>(v, attn, ctx, attn, maskp);
}

// round 16
// speedup vs baseline: 2.8881x; 2.8881x over previous
#include <cuda_runtime.h>
#include <cstdint>

#define SEQ 2048
#define HD 64
#define NBH 32
#define TOPK 32
#define WPB 4
#define LCAP 128
#define CCAP 128
#define NROWS (NBH * SEQ)

typedef unsigned long long u64;

__device__ __forceinline__ u64 dup2(float x) {
    u64 r; asm("mov.b64 %0, {%1, %1};" : "=l"(r) : "f"(x)); return r;
}
__device__ __forceinline__ void fma2(u64& c, u64 a, u64 b) {
    asm("fma.rn.f32x2 %0, %1, %2, %0;" : "+l"(c) : "l"(a), "l"(b));
}
__device__ __forceinline__ unsigned fkey(float f) {
    unsigned u = __float_as_uint(f);
    return (u & 0x80000000u) ? ~u : (u | 0x80000000u);
}

// ---------------------------------------------------------------------------
// Kernel 1 (R10, measured ~571us): scores = (q/8).k via packed f32x2 FMA.
// 128(i) x 64(j) tile, 128 threads, 8x8 microtile. Prefills mask=1 (streaming).
// ---------------------------------------------------------------------------
__global__ __launch_bounds__(128) void score_kernel(
    const float* __restrict__ q, const float* __restrict__ k,
    float* __restrict__ scores, float* __restrict__ maskp)
{
    __shared__ float QsT[HD * 128];
    __shared__ float KsT[HD * 64];

    const int t = threadIdx.x;
    const int bh = blockIdx.z;
    const float* qb = q + ((size_t)bh * SEQ + blockIdx.y * 128) * HD;
    const float* kb = k + ((size_t)bh * SEQ + blockIdx.x * 64) * HD;

#pragma unroll
    for (int it = 0; it < 16; it++) {
        int idx = t + 128 * it;
        int d4 = idx >> 7, row = idx & 127;
        float4 val = *(const float4*)(qb + row * HD + d4 * 4);
        QsT[(d4 * 4 + 0) * 128 + row] = val.x * 0.125f;
        QsT[(d4 * 4 + 1) * 128 + row] = val.y * 0.125f;
        QsT[(d4 * 4 + 2) * 128 + row] = val.z * 0.125f;
        QsT[(d4 * 4 + 3) * 128 + row] = val.w * 0.125f;
    }
#pragma unroll
    for (int it = 0; it < 8; it++) {
        int idx = t + 128 * it;
        int d4 = idx >> 6, row = idx & 63;
        float4 val = *(const float4*)(kb + row * HD + d4 * 4);
        KsT[(d4 * 4 + 0) * 64 + row] = val.x;
        KsT[(d4 * 4 + 1) * 64 + row] = val.y;
        KsT[(d4 * 4 + 2) * 64 + row] = val.z;
        KsT[(d4 * 4 + 3) * 64 + row] = val.w;
    }
    __syncthreads();

    const int ti = t >> 3, tj = t & 7;
    u64 acc[8][4];
#pragma unroll
    for (int i = 0; i < 8; i++)
#pragma unroll
        for (int p = 0; p < 4; p++) acc[i][p] = 0ull;

    const float4* Q4 = (const float4*)QsT;
    const u64* K2 = (const u64*)KsT;

#pragma unroll 8
    for (int d = 0; d < HD; d++) {
        float4 a0 = Q4[d * 32 + ti * 2];
        float4 a1 = Q4[d * 32 + ti * 2 + 1];
        u64 b0 = K2[d * 32 + tj * 4 + 0];
        u64 b1 = K2[d * 32 + tj * 4 + 1];
        u64 b2 = K2[d * 32 + tj * 4 + 2];
        u64 b3 = K2[d * 32 + tj * 4 + 3];
        float av[8] = {a0.x, a0.y, a0.z, a0.w, a1.x, a1.y, a1.z, a1.w};
#pragma unroll
        for (int i = 0; i < 8; i++) {
            u64 ai = dup2(av[i]);
            fma2(acc[i][0], ai, b0);
            fma2(acc[i][1], ai, b1);
            fma2(acc[i][2], ai, b2);
            fma2(acc[i][3], ai, b3);
        }
    }

    const size_t obase = ((size_t)bh * SEQ + blockIdx.y * 128 + ti * 8) * SEQ
                       + blockIdx.x * 64 + tj * 8;
#pragma unroll
    for (int i = 0; i < 8; i++) {
        u64* o = (u64*)(scores + obase + (size_t)i * SEQ);
        o[0] = acc[i][0]; o[1] = acc[i][1]; o[2] = acc[i][2]; o[3] = acc[i][3];
    }
    if (maskp) {
        const float4 one4 = make_float4(1.f, 1.f, 1.f, 1.f);
#pragma unroll
        for (int i = 0; i < 8; i++) {
            float4* mo = (float4*)(maskp + obase + (size_t)i * SEQ);
            __stcs(mo, one4); __stcs(mo + 1, one4);
        }
    }
}

// Pick the bin (0..255) holding the kk-th largest, given a 256-bin histogram.
__device__ __forceinline__ void pick_bin(unsigned* H, int lane, unsigned kkin,
                                         unsigned& bin, unsigned& kkout)
{
    unsigned p = 0;
#pragma unroll
    for (int b = 0; b < 8; b++) p += H[lane * 8 + b];
    unsigned S = p;
#pragma unroll
    for (int off = 1; off < 32; off <<= 1) {
        unsigned tv = __shfl_down_sync(0xffffffffu, S, off);
        if (lane + off < 32) S += tv;
    }
    unsigned sufExcl = S - p;
    bool mine = (S >= kkin) && (sufExcl < kkin);
    unsigned bal = __ballot_sync(0xffffffffu, mine);
    int src = __ffs(bal) - 1;
    unsigned chosen = 0, newk = 0;
    if (mine) {
        unsigned cum = sufExcl;
#pragma unroll
        for (int b = 7; b >= 0; b--) {
            unsigned h = H[lane * 8 + b];
            if (cum + h >= kkin) { chosen = lane * 8 + b; newk = kkin - cum; break; }
            cum += h;
        }
    }
    bin = __shfl_sync(0xffffffffu, chosen, src);
    kkout = __shfl_sync(0xffffffffu, newk, src);
}

// ---------------------------------------------------------------------------
// Kernel 2: warp-per-row, u16 key digest (top 16 bits) in smem, PLAIN smem
// atomics (match_any was a measured 4x pessimization). Rounds 1-2 exact on
// the digest; candidates (top16 == prefix16) refetched once from the L2-hot
// gmem row, exact rounds 3-4 over them. Ties in the keep-scan resolved by
// exact refetch. ALL refetches precede the in-place attn=0 fill.
// 26KB smem/block -> 8 blocks/SM (32 warps vs R10's 20).
// ---------------------------------------------------------------------------
__global__ __launch_bounds__(WPB * 32) void finalize_kernel(
    const float* __restrict__ v, const float* __restrict__ scores,
    float* __restrict__ ctx, float* __restrict__ attn, float* __restrict__ maskp)
{
    __shared__ unsigned short srow16[WPB][SEQ];   // 16 KB
    __shared__ unsigned hist[WPB][256];           // 4 KB
    __shared__ unsigned candk[WPB][CCAP];         // 2 KB
    __shared__ int list[WPB][LCAP];               // 2 KB
    __shared__ float plist[WPB][LCAP];            // 2 KB

    const int w = threadIdx.x >> 5;
    const int lane = threadIdx.x & 31;
    const size_t R = (size_t)(NROWS - 1) - ((size_t)blockIdx.x * WPB + w);
    const int bh = (int)(R >> 11);
    const float* grow = scores + R * SEQ;
    unsigned* H = hist[w];

#define HADD(binv, active) { if (active) atomicAdd(&H[(binv)], 1u); }

    // ---- Pass 1: digest + exact max + top-byte histogram ----
#pragma unroll
    for (int e = 0; e < 8; e++) H[lane + 32 * e] = 0;
    __syncwarp();
    const float4* g4 = (const float4*)grow;
    float m = __int_as_float(0xff800000);
#pragma unroll 4
    for (int it = 0; it < 16; it++) {
        float4 val = g4[lane + 32 * it];
        m = fmaxf(m, fmaxf(fmaxf(val.x, val.y), fmaxf(val.z, val.w)));
        unsigned k0 = fkey(val.x), k1 = fkey(val.y), k2 = fkey(val.z), k3 = fkey(val.w);
        ushort4 h4;
        h4.x = (unsigned short)(k0 >> 16); h4.y = (unsigned short)(k1 >> 16);
        h4.z = (unsigned short)(k2 >> 16); h4.w = (unsigned short)(k3 >> 16);
        ((ushort4*)srow16[w])[lane + 32 * it] = h4;
        HADD(k0 >> 24, true); HADD(k1 >> 24, true);
        HADD(k2 >> 24, true); HADD(k3 >> 24, true);
    }
#pragma unroll
    for (int off = 16; off >= 1; off >>= 1)
        m = fmaxf(m, __shfl_xor_sync(0xffffffffu, m, off));
    __syncwarp();

    // ---- Round 1 ----
    unsigned kk = TOPK, b1, b2;
    pick_bin(H, lane, kk, b1, kk);
    __syncwarp();

    // ---- Round 2: byte2 histogram over digest where top byte == b1 ----
#pragma unroll
    for (int e = 0; e < 8; e++) H[lane + 32 * e] = 0;
    __syncwarp();
    const unsigned* s32 = (const unsigned*)srow16[w];   // 1024 packed pairs
#pragma unroll 4
    for (int it = 0; it < 32; it++) {
        unsigned u = s32[lane + 32 * it];
        unsigned lo = u & 0xFFFFu, hi = u >> 16;
        HADD(lo & 255u, (lo >> 8) == b1);
        HADD(hi & 255u, (hi >> 8) == b1);
    }
    __syncwarp();
    pick_bin(H, lane, kk, b2, kk);
    const unsigned prefix16 = (b1 << 8) | b2;
    __syncwarp();

    // ---- Collect candidates (digest == prefix16): exact keys via refetch ----
    int cbase = 0;
    for (int it = 0; it < 32; it++) {
        unsigned u = s32[lane + 32 * it];
#pragma unroll
        for (int h = 0; h < 2; h++) {
            unsigned hv = h ? (u >> 16) : (u & 0xFFFFu);
            int j = (lane + 32 * it) * 2 + h;
            bool isc = (hv == prefix16);
            unsigned bal = __ballot_sync(0xffffffffu, isc);
            if (isc) {
                int pos = cbase + __popc(bal & ((1u << lane) - 1u));
                if (pos < CCAP) candk[w][pos] = fkey(__ldg(&grow[j]));
            }
            cbase += __popc(bal);
        }
    }
    __syncwarp();

    unsigned tkey;
    if (cbase <= CCAP) {
        const int c = cbase;
        // ---- Round 3 over candidates (byte1 of exact key) ----
#pragma unroll
        for (int e = 0; e < 8; e++) H[lane + 32 * e] = 0;
        __syncwarp();
        for (int e = lane; e < c; e += 32) {
            unsigned u = candk[w][e];
            atomicAdd(&H[(u >> 8) & 255u], 1u);
        }
        __syncwarp();
        unsigned b3;
        pick_bin(H, lane, kk, b3, kk);
        __syncwarp();
        // ---- Round 4 (byte0 where byte1 == b3) ----
#pragma unroll
        for (int e = 0; e < 8; e++) H[lane + 32 * e] = 0;
        __syncwarp();
        for (int e = lane; e < c; e += 32) {
            unsigned u = candk[w][e];
            if (((u >> 8) & 255u) == b3) atomicAdd(&H[u & 255u], 1u);
        }
        __syncwarp();
        unsigned b4, kkd;
        pick_bin(H, lane, kk, b4, kkd);
        tkey = (prefix16 << 16) | (b3 << 8) | b4;
    } else {
        // Exact fallback (pathological tie storm): full-row rounds 3-4 from gmem.
        unsigned prefix = prefix16 << 16, prefmask = 0xFFFF0000u;
#pragma unroll
        for (int shift = 8; shift >= 0; shift -= 8) {
#pragma unroll
            for (int e = 0; e < 8; e++) H[lane + 32 * e] = 0;
            __syncwarp();
            for (int it = 0; it < 16; it++) {
                float4 val = g4[lane + 32 * it];
                unsigned ks[4] = {fkey(val.x), fkey(val.y), fkey(val.z), fkey(val.w)};
#pragma unroll
                for (int cc = 0; cc < 4; cc++)
                    HADD((ks[cc] >> shift) & 255u, (ks[cc] & prefmask) == prefix);
            }
            __syncwarp();
            unsigned bsel;
            pick_bin(H, lane, kk, bsel, kk);
            prefix |= bsel << shift;
            prefmask |= 0xFFu << shift;
            __syncwarp();
        }
        tkey = prefix;
    }
    const unsigned thr16 = tkey >> 16;   // == prefix16
    __syncwarp();

    // ---- Keep-scan (digest; ties resolved by exact refetch) ----
    int base = 0;
    for (int it = 0; it < 32; it++) {
        unsigned u = s32[lane + 32 * it];
#pragma unroll
        for (int h = 0; h < 2; h++) {
            unsigned hv = h ? (u >> 16) : (u & 0xFFFFu);
            int j = (lane + 32 * it) * 2 + h;
            bool keep = (hv > thr16);
            if (hv == thr16) keep = fkey(__ldg(&grow[j])) >= tkey;
            unsigned bal = __ballot_sync(0xffffffffu, keep);
            if (keep) {
                int pos = base + __popc(bal & ((1u << lane) - 1u));
                if (pos < LCAP) list[w][pos] = j;
            }
            base += __popc(bal);
        }
    }
    __syncwarp();
    const int n = base < LCAP ? base : LCAP;

    // ---- exp on kept (raw scores from L1/L2-hot gmem, BEFORE the fill) ----
    float lsum = 0.f;
    for (int e = lane; e < n; e += 32) {
        float s = __ldg(&grow[list[w][e]]);
        float p = __expf(s - m);
        plist[w][e] = p;
        lsum += p;
    }
#pragma unroll
    for (int off = 16; off >= 1; off >>= 1)
        lsum += __shfl_xor_sync(0xffffffffu, lsum, off);
    const float inv = 1.0f / lsum;
    __syncwarp();

    // ---- attn = 0 fill (in-place overwrite of the score row) ----
    float4* a4 = (float4*)(attn + R * SEQ);
    const float4 zero4 = make_float4(0.f, 0.f, 0.f, 0.f);
#pragma unroll
    for (int it = 0; it < 16; it++) __stcs(&a4[lane + 32 * it], zero4);

    // ---- Scatter kept attn / mask=0; dual-accumulator V gather ----
    const float* vb = v + (size_t)bh * SEQ * HD;
    float acc0a = 0.f, acc1a = 0.f, acc0b = 0.f, acc1b = 0.f;
    float* arow = attn + R * SEQ;
    float* mrow = maskp ? maskp + R * SEQ : (float*)0;
    int e = 0;
    for (; e + 1 < n; e += 2) {
        int j0 = list[w][e], j1 = list[w][e + 1];
        float w0 = plist[w][e] * inv, w1 = plist[w][e + 1] * inv;
        float v00 = __ldg(vb + j0 * HD + lane);
        float v01 = __ldg(vb + j0 * HD + lane + 32);
        float v10 = __ldg(vb + j1 * HD + lane);
        float v11 = __ldg(vb + j1 * HD + lane + 32);
        if (lane == 0) {
            arow[j0] = w0; arow[j1] = w1;
            if (mrow) { mrow[j0] = 0.f; mrow[j1] = 0.f; }
        }
        acc0a += w0 * v00; acc1a += w0 * v01;
        acc0b += w1 * v10; acc1b += w1 * v11;
    }
    if (e < n) {
        int j0 = list[w][e];
        float w0 = plist[w][e] * inv;
        if (lane == 0) {
            arow[j0] = w0;
            if (mrow) mrow[j0] = 0.f;
        }
        acc0a += w0 * __ldg(vb + j0 * HD + lane);
        acc1a += w0 * __ldg(vb + j0 * HD + lane + 32);
    }
    if (ctx) {
        ctx[R * HD + lane] = acc0a + acc0b;
        ctx[R * HD + lane + 32] = acc1a + acc1b;
    }
#undef HADD
}

// ---------------------------------------------------------------------------
extern "C" void kernel_launch(void* const* d_in, const int* in_sizes, int n_in,
                              void* d_out, int out_size)
{
    if (n_in < 3 || !d_out) return;
    const float* q = (const float*)d_in[0];
    const float* k = (const float*)d_in[1];
    const float* v = (const float*)d_in[2];
    float* out = (float*)d_out;

    const size_t nctx = (size_t)NBH * SEQ * HD;        //   4,194,304
    const size_t nattn = (size_t)NBH * SEQ * SEQ;      // 134,217,728
    float* ctx = 0; float* attn = 0; float* maskp = 0;
    const size_t osz = (size_t)out_size;
    if (osz >= nctx + 2 * nattn) {
        ctx = out; attn = out + nctx; maskp = out + nctx + nattn;
    } else if (osz >= nctx + nattn) {
        ctx = out; attn = out + nctx;
    } else {
        attn = out;
    }

    // Kernel 1 stages raw scores in the attn segment and prefills mask = 1.
    score_kernel<<<dim3(SEQ / 64, SEQ / 128, NBH), 128>>>(q, k, attn, maskp);
    finalize_kernel<<<NROWS / WPB, WPB * 32>>>(v, attn, ctx, attn, maskp);
}